// round 15
// baseline (speedup 1.0000x reference)
#include <cuda_runtime.h>
#include <cuda_bf16.h>
#include <cuda_pipeline.h>
#include <math.h>

// SwitchMoE with the reference's dim-1 scatter gate bug:
//   mask[b, top1[b,n], 0] = 1  =>  output nonzero only for n<8, expert 0.
// E=8, DIM=128, HID=512, OUT=128, B=16, H=W=64, N=4096.
//
// 2 launches:
//   K1 (grid 640 x 128thr): blocks <512 = warp-autonomous gate (4-stage
//       cp.async.cg ring, FFMA2 packed accumulators) + interleaved streaming
//       zero-stores of out; blocks >=512 = expert-0 fc1 at 18 pixels/batch.
//   K2 (grid 1024 x 128thr): block = (b, j, out-eighth). W2 slice (32 KB)
//       staged to smem via cp.async AT ENTRY (hides W2 latency behind
//       mask+conv+GELU); fc2 entirely from smem.

#define BATCH 16
#define NTOK  4096
#define DIM   128
#define NEXP  8
#define HID   512
#define OUTD  128
#define EPS   1e-6f

// ---- scratch (device globals; every element rewritten each call) ----
__device__ unsigned g_bm[512];                    // per-gate-block OR of (1<<argmax)
__device__ float    g_prob0[BATCH * NEXP];        // softmax p(expert0) at token n<8
__device__ float    g_h1[BATCH * 2 * 9 * HID];    // expert-0 fc1 at (h in {0,1}, w in [0,9))

#define FMA2(acc, a, b) \
    asm("fma.rn.f32x2 %0, %1, %2, %0;" : "+l"(acc) : "l"(a), "l"(b))

// cp.async.cg: 16B global->shared, L2-only (no L1 allocate) — streaming reads
__device__ __forceinline__ void cp_cg16(void* dst_smem, const void* src) {
    unsigned d = (unsigned)__cvta_generic_to_shared(dst_smem);
    asm volatile("cp.async.cg.shared.global [%0], [%1], 16;" :: "r"(d), "l"(src));
}

// evict-first streaming store (dead data: nobody reads the zeros back)
__device__ __forceinline__ void stg_cs_zero(float4* p) {
    asm volatile("st.global.cs.v4.f32 [%0], {%1,%1,%1,%1};" :: "l"(p), "f"(0.0f));
}

// ------------------------------------------------------------------
// K1: warp-autonomous gate (+ interleaved streaming zeroing) and fc1
// ------------------------------------------------------------------
__global__ void __launch_bounds__(128, 5) gate_fc1_kernel(
    const float* __restrict__ x, const float* __restrict__ wg,
    const float* __restrict__ bg, const float* __restrict__ W1,
    const float* __restrict__ B1, float* __restrict__ out)
{
    // pool aliasing:
    //   gate: wg_s[1024] | bg_s[8] | xs[4 warps][4 stages][32*20] = 11272 floats
    //   fc1 : xs18[18*128] = 2304 floats
    __shared__ float pool[11272];
    __shared__ unsigned warpor[4];

    const int tid = threadIdx.x;
    const int blk = blockIdx.x;

    if (blk < 512) {
        // ================= gate path =================
        float* wg_s = pool;                          // [DIM*NEXP]
        float* bg_s = pool + 1024;                   // [NEXP]
        const int wid = tid >> 5, lane = tid & 31;
        float* xw = pool + 1032 + wid * (4 * 640);   // this warp's 4-stage ring

        const int tok0 = blk * 128;
        const float* xb = x + (size_t)(tok0 + wid * 32) * DIM;  // warp's 32 tokens
        float4* ob = (float4*)(out + (size_t)tok0 * OUTD);      // block's 128 out rows

        for (int i = tid; i < DIM * NEXP; i += 128) wg_s[i] = wg[i];
        if (tid < NEXP) bg_s[tid] = bg[tid];
        __syncthreads();                             // wg_s ready; warps go autonomous

        // staging coords: lane copies quarter q of tokens tq, tq+8, tq+16, tq+24
        const int tq = lane >> 2, q = lane & 3;

        // prologue: stage chunks 0..2 (each chunk = 32 tokens x 16 dims)
#pragma unroll
        for (int ch = 0; ch < 3; ch++) {
            float* dst = xw + ch * 640;
#pragma unroll
            for (int k = 0; k < 4; k++) {
                int t = tq + 8 * k;
                cp_cg16(dst + t * 20 + q * 4,
                        xb + (size_t)t * DIM + ch * 16 + q * 4);
            }
            __pipeline_commit();
        }

        // packed accumulators: (e0,e1) (e2,e3) (e4,e5) (e6,e7)
        unsigned long long a01 = 0ull, a23 = 0ull, a45 = 0ull, a67 = 0ull;

#pragma unroll
        for (int ch = 0; ch < 8; ch++) {
            if (ch < 5) {                            // stage chunk ch+3
                float* dst = xw + ((ch + 3) & 3) * 640;
#pragma unroll
                for (int k = 0; k < 4; k++) {
                    int t = tq + 8 * k;
                    cp_cg16(dst + t * 20 + q * 4,
                            xb + (size_t)t * DIM + (ch + 3) * 16 + q * 4);
                }
                __pipeline_commit();
                __pipeline_wait_prior(3);            // chunk ch landed
            } else {
                __pipeline_wait_prior(7 - ch);
            }
            __syncwarp();

            const float* buf = xw + (ch & 3) * 640;
#pragma unroll
            for (int d4 = 0; d4 < 4; d4++) {
                float4 xv = *(const float4*)(buf + lane * 20 + d4 * 4);
                float xarr[4] = {xv.x, xv.y, xv.z, xv.w};
#pragma unroll
                for (int jj = 0; jj < 4; jj++) {
                    int dd = ch * 16 + d4 * 4 + jj;
                    const ulonglong2* wrow = (const ulonglong2*)(wg_s + dd * 8);
                    ulonglong2 wa = wrow[0];
                    ulonglong2 wb = wrow[1];
                    unsigned long long xd2;
                    asm("mov.b64 %0, {%1, %1};" : "=l"(xd2) : "f"(xarr[jj]));
                    FMA2(a01, xd2, wa.x);
                    FMA2(a23, xd2, wa.y);
                    FMA2(a45, xd2, wb.x);
                    FMA2(a67, xd2, wb.y);
                }
            }
            __syncwarp();                            // done reading buf before re-fill

            // interleaved streaming zero-stores: 4 float4 per thread per chunk
#pragma unroll
            for (int k = 0; k < 4; k++)
                stg_cs_zero(ob + ch * 512 + k * 128 + tid);
        }

        // unpack logits, add bias; first-max argmax (matches jnp.argmax)
        float l[NEXP];
        asm("mov.b64 {%0, %1}, %2;" : "=f"(l[0]), "=f"(l[1]) : "l"(a01));
        asm("mov.b64 {%0, %1}, %2;" : "=f"(l[2]), "=f"(l[3]) : "l"(a23));
        asm("mov.b64 {%0, %1}, %2;" : "=f"(l[4]), "=f"(l[5]) : "l"(a45));
        asm("mov.b64 {%0, %1}, %2;" : "=f"(l[6]), "=f"(l[7]) : "l"(a67));
#pragma unroll
        for (int e = 0; e < NEXP; e++) l[e] += bg_s[e];
        float m = l[0]; int am = 0;
#pragma unroll
        for (int e = 1; e < NEXP; e++) if (l[e] > m) { m = l[e]; am = e; }

        const int tok = tok0 + tid;                  // wid*32+lane == tid
        const int b = tok >> 12;
        const int n = tok & (NTOK - 1);
        if (n < NEXP) {
            float s = 0.0f;
#pragma unroll
            for (int e = 0; e < NEXP; e++) s += expf(l[e] - m);
            g_prob0[b * NEXP + n] = expf(l[0] - m) / s;
        }

        // per-block argmax bitmask (replay-safe: every slot rewritten each call)
        unsigned wor = __reduce_or_sync(0xffffffffu, 1u << am);
        if (lane == 0) warpor[wid] = wor;
        __syncthreads();
        if (tid == 0)
            g_bm[blk] = warpor[0] | warpor[1] | warpor[2] | warpor[3];
    } else {
        // ================= fc1 path =================
        // expert-0 fc1 at 18 pixels/batch: h in {0,1}, w in [0,9)
        float* xs = pool;                            // [18*DIM]
        const int bb = blk - 512;                    // [0,128)
        const int b  = bb >> 3, cg = bb & 7;

        for (int i = tid; i < 18 * DIM; i += 128) {
            int p = i >> 7, d = i & (DIM - 1);
            int h = p / 9, w = p % 9;
            int nn = h * 64 + w;
            xs[p * DIM + d] = x[((size_t)b * NTOK + nn) * DIM + d];
        }
        __syncthreads();

        const int c  = cg * 64 + (tid & 63);
        const int t0 = tid >> 6;                     // tokens t0, t0+2, ..., t0+16

        float acc9[9];
        float bv = B1[c];
#pragma unroll
        for (int k = 0; k < 9; k++) acc9[k] = bv;

        for (int d4 = 0; d4 < DIM / 4; d4++) {
            float4 xv[9];
#pragma unroll
            for (int k = 0; k < 9; k++)
                xv[k] = *(const float4*)(xs + (t0 + 2 * k) * DIM + d4 * 4);
#pragma unroll
            for (int j = 0; j < 4; j++) {
                float w = W1[(size_t)(d4 * 4 + j) * HID + c];
#pragma unroll
                for (int k = 0; k < 9; k++) {
                    float xd = ((const float*)&xv[k])[j];
                    acc9[k] += xd * w;
                }
            }
        }

#pragma unroll
        for (int k = 0; k < 9; k++) {
            int p = t0 + 2 * k;
            int h = p / 9, w = p % 9;
            g_h1[(((size_t)b * 2 + h) * 9 + w) * HID + c] = acc9[k];
        }
    }
}

// ------------------------------------------------------------------
// K2: block = (b, j, out-eighth q). Stage W2[:, 16q:16q+16) (32 KB) to smem
// via cp.async at entry; mask + dwconv + GELU overlap the staging; fc2 from
// smem; 16 threads store the 16 outputs.
// ------------------------------------------------------------------
__global__ void __launch_bounds__(128, 6) out_kernel(
    const float* __restrict__ Wd, const float* __restrict__ Bd,
    const float* __restrict__ W2, const float* __restrict__ B2,
    float* __restrict__ out)
{
    __shared__ float W2s[HID * 16];                  // 32 KB
    __shared__ float gs[HID];
    __shared__ float partial[8 * 16];
    __shared__ unsigned mor[BATCH];

    const int tid = threadIdx.x;
    const int blk = blockIdx.x;
    const int q = blk & 7;                           // out-eighth
    const int j = (blk >> 3) & 7;
    const int b = blk >> 6;

    // ---- stage W2 slice first: latency hides behind mask+conv ----
#pragma unroll
    for (int k = 0; k < 16; k++) {
        int idx = tid + k * 128;
        int row = idx >> 2, part = idx & 3;
        cp_cg16(W2s + row * 16 + part * 4,
                W2 + (size_t)row * OUTD + q * 16 + part * 4);
    }
    __pipeline_commit();

    // ---- mask: warp w owns batches w, w+4, w+8, w+12 (32 gate blocks each) ----
    {
        const int wid = tid >> 5;
#pragma unroll
        for (int k = 0; k < 4; k++) {
            unsigned m = __reduce_or_sync(0xffffffffu, g_bm[tid + k * 128]);
            if ((tid & 31) == 0) mor[wid + 4 * k] = m;
        }
    }

    // ---- depthwise conv at (h=0, w=j) + exact GELU, 4 channels/thread ----
#pragma unroll
    for (int k = 0; k < 4; k++) {
        int c = tid + k * 128;
        float conv = Bd[c];
#pragma unroll
        for (int hh = 0; hh < 2; hh++) {
#pragma unroll
            for (int kw = 0; kw < 3; kw++) {
                int wp = j + kw - 1;
                if (wp >= 0 && wp <= 8) {
                    conv += g_h1[(((size_t)b * 2 + hh) * 9 + wp) * HID + c]
                          * Wd[((hh + 1) * 3 + kw) * HID + c];
                }
            }
        }
        gs[c] = 0.5f * conv * (1.0f + erff(conv * 0.70710678118654752f));
    }

    __pipeline_wait_prior(0);                        // W2 slice landed
    __syncthreads();                                 // gs + W2s + mor visible

    // ---- fc2 partials from smem: thread = (c-slice s of 64, out o of 16) ----
    {
        const int o = tid & 15, s = tid >> 4;
        const float* wp = W2s + (s * 64) * 16 + o;
        const float* gp = gs + s * 64;
        float acc = 0.0f;
#pragma unroll
        for (int i = 0; i < 64; i++)
            acc += gp[i] * wp[i * 16];
        partial[s * 16 + o] = acc;
    }
    __syncthreads();

    // ---- reduce + gate + store: 16 threads, one output each ----
    if (tid < 16) {
        float s = 0.0f;
#pragma unroll
        for (int bb = 0; bb < BATCH; bb++)
            s += g_prob0[bb * NEXP + j] * (float)((mor[bb] >> j) & 1u);
        float gv = g_prob0[b * NEXP + j] * (float)((mor[b] >> j) & 1u);
        float gate_s = gv / (s + EPS) * (float)BATCH;   // capacity = 16.0

        float acc = B2[q * 16 + tid];
#pragma unroll
        for (int sl = 0; sl < 8; sl++) acc += partial[sl * 16 + tid];

        out[((size_t)b * NTOK + j) * OUTD + q * 16 + tid] = gate_s * acc;
    }
}

// ------------------------------------------------------------------
extern "C" void kernel_launch(void* const* d_in, const int* in_sizes, int n_in,
                              void* d_out, int out_size)
{
    // input order: x, [H, W,] wg, bg, W1, B1, Wd, Bd, W2, B2
    int o = (n_in >= 11) ? 3 : 1;
    const float* x  = (const float*)d_in[0];
    const float* wg = (const float*)d_in[o + 0];
    const float* bg = (const float*)d_in[o + 1];
    const float* W1 = (const float*)d_in[o + 2];
    const float* B1 = (const float*)d_in[o + 3];
    const float* Wd = (const float*)d_in[o + 4];
    const float* Bd = (const float*)d_in[o + 5];
    const float* W2 = (const float*)d_in[o + 6];
    const float* B2 = (const float*)d_in[o + 7];
    float* out = (float*)d_out;

    gate_fc1_kernel<<<640, 128>>>(x, wg, bg, W1, B1, out);
    out_kernel<<<1024, 128>>>(Wd, Bd, W2, B2, out);
}